// round 7
// baseline (speedup 1.0000x reference)
#include <cuda_runtime.h>
#include <cuda_bf16.h>

// Problem constants
#define T_DIM 2048
#define B_DIM 4
#define E_DIM 512
#define H_DIM 8
#define HG 4                            // heads per group (S holds HG heads)
#define HD_DIM 64
#define BH_DIM (B_DIM * H_DIM)
#define TT ((size_t)T_DIM * T_DIM)      // 1<<22
#define ROWS (T_DIM * B_DIM)            // 8192
#define SCALE 0.125f
#define SPAD 68                         // scores smem stride
#define AV_PS 36                        // attnv P smem stride (bank = 4g+q4)
#define AV_VS 72                        // attnv V smem stride (bank = 8q4+g)
#define KSPLIT 4

// ---------------- static device scratch (~187 MB) ----------------
__device__ float g_Q[(size_t)BH_DIM * T_DIM * HD_DIM];   // 16.8 MB (tf32-rounded, *SCALE)
__device__ float g_K[(size_t)BH_DIM * T_DIM * HD_DIM];   // 16.8 MB (tf32-rounded)
__device__ float g_V[(size_t)BH_DIM * T_DIM * HD_DIM];   // 16.8 MB (tf32-rounded)
__device__ float g_S[(size_t)HG * TT];                   // 67.1 MB
__device__ float g_ctx[KSPLIT][(size_t)ROWS * E_DIM];    // 67.1 MB (4 k-slices)
__device__ float g_pm[(size_t)HG * T_DIM * 32];          // 1 MB
__device__ float g_ps[(size_t)HG * T_DIM * 32];          // 1 MB
__device__ float g_m[HG * T_DIM];
__device__ float g_inv[HG * T_DIM];

// ---------------- helpers ----------------
__device__ __forceinline__ unsigned f2tf(float x) {
    unsigned u; asm("cvt.rna.tf32.f32 %0, %1;" : "=r"(u) : "f"(x)); return u;
}
__device__ __forceinline__ void mma_tf32(float* d,
    unsigned a0, unsigned a1, unsigned a2, unsigned a3,
    unsigned b0, unsigned b1)
{
    asm volatile(
        "mma.sync.aligned.m16n8k8.row.col.f32.tf32.tf32.f32 "
        "{%0,%1,%2,%3}, {%4,%5,%6,%7}, {%8,%9}, {%0,%1,%2,%3};\n"
        : "+f"(d[0]), "+f"(d[1]), "+f"(d[2]), "+f"(d[3])
        : "r"(a0), "r"(a1), "r"(a2), "r"(a3), "r"(b0), "r"(b1));
}
__device__ __forceinline__ void cpa16(unsigned dst, const float* src) {
    asm volatile("cp.async.ca.shared.global [%0], [%1], 16;" :: "r"(dst), "l"(src));
}

// =====================================================================
// Kernel 1: QKV projection (fp32 FFMA).  Outputs pre-rounded to tf32.
// =====================================================================
__global__ __launch_bounds__(256) void qkv_kernel(
    const float* __restrict__ x, const float* __restrict__ W,
    const float* __restrict__ bias)
{
    __shared__ float As[64][33];
    __shared__ float Bs[64][33];
    const int tid = threadIdx.x;
    const int tx = tid & 15, ty = tid >> 4;
    const int row0 = blockIdx.x * 64;
    const int col0 = blockIdx.y * 64;

    float acc[4][4] = {};
    for (int k0 = 0; k0 < E_DIM; k0 += 32) {
        #pragma unroll
        for (int l = tid; l < 512; l += 256) {
            int r = l >> 3, kv = l & 7;
            float4 v = *reinterpret_cast<const float4*>(&x[(size_t)(row0 + r) * E_DIM + k0 + 4 * kv]);
            As[r][4 * kv + 0] = v.x; As[r][4 * kv + 1] = v.y;
            As[r][4 * kv + 2] = v.z; As[r][4 * kv + 3] = v.w;
        }
        #pragma unroll
        for (int l = tid; l < 512; l += 256) {
            int n = l >> 3, kv = l & 7;
            float4 v = *reinterpret_cast<const float4*>(&W[(size_t)(col0 + n) * E_DIM + k0 + 4 * kv]);
            Bs[n][4 * kv + 0] = v.x; Bs[n][4 * kv + 1] = v.y;
            Bs[n][4 * kv + 2] = v.z; Bs[n][4 * kv + 3] = v.w;
        }
        __syncthreads();
        #pragma unroll
        for (int kk = 0; kk < 32; kk++) {
            float a[4], b[4];
            #pragma unroll
            for (int i = 0; i < 4; i++) a[i] = As[4 * ty + i][kk];
            #pragma unroll
            for (int j = 0; j < 4; j++) b[j] = Bs[4 * tx + j][kk];
            #pragma unroll
            for (int i = 0; i < 4; i++)
                #pragma unroll
                for (int j = 0; j < 4; j++) acc[i][j] += a[i] * b[j];
        }
        __syncthreads();
    }

    #pragma unroll
    for (int i = 0; i < 4; i++) {
        int r = row0 + 4 * ty + i;
        int t = r >> 2, b = r & 3;
        #pragma unroll
        for (int j = 0; j < 4; j++) {
            int n = col0 + 4 * tx + j;
            float val = acc[i][j] + bias[n];
            if (n < 512) {
                int h = n >> 6, d = n & 63;
                g_Q[(((size_t)(b * H_DIM + h) * T_DIM) + t) * HD_DIM + d] =
                    __uint_as_float(f2tf(val * SCALE));
            } else if (n < 1024) {
                int n2 = n - 512;
                int h = n2 >> 6, d = n2 & 63;
                g_K[(((size_t)(b * H_DIM + h) * T_DIM) + t) * HD_DIM + d] =
                    __uint_as_float(f2tf(val));
            } else {
                int n2 = n - 1024;
                int h = n2 >> 6, d = n2 & 63;
                g_V[(((size_t)(b * H_DIM + h) * T_DIM) + t) * HD_DIM + d] =
                    __uint_as_float(f2tf(val));
            }
        }
    }
}

// =====================================================================
// Kernel 2: scores (tf32 MMA, inputs pre-rounded) + fused softmax partials
// =====================================================================
__global__ __launch_bounds__(256) void scores_tf32(int b, int hg)
{
    __shared__ unsigned Qs[64 * SPAD];
    __shared__ unsigned Ks[64 * SPAD];
    __shared__ float sm_m[64][4], sm_s[64][4];
    const int tid = threadIdx.x;
    const int lane = tid & 31, warp = tid >> 5;
    const int wm = warp >> 2, wn = warp & 3;
    const int g = lane >> 2, q4 = lane & 3;
    const int hl = blockIdx.z;
    const int bh = b * H_DIM + hg * HG + hl;
    const int row0 = blockIdx.x * 64;
    const int col0 = blockIdx.y * 64;
    const unsigned* Qp = reinterpret_cast<const unsigned*>(g_Q) + (size_t)bh * T_DIM * HD_DIM;
    const unsigned* Kp = reinterpret_cast<const unsigned*>(g_K) + (size_t)bh * T_DIM * HD_DIM;

    #pragma unroll
    for (int l = tid; l < 1024; l += 256) {
        int r = l >> 4, c4 = l & 15;
        uint4 v = *reinterpret_cast<const uint4*>(&Qp[(size_t)(row0 + r) * HD_DIM + 4 * c4]);
        Qs[r * SPAD + 4 * c4 + 0] = v.x; Qs[r * SPAD + 4 * c4 + 1] = v.y;
        Qs[r * SPAD + 4 * c4 + 2] = v.z; Qs[r * SPAD + 4 * c4 + 3] = v.w;
    }
    #pragma unroll
    for (int l = tid; l < 1024; l += 256) {
        int r = l >> 4, c4 = l & 15;
        uint4 v = *reinterpret_cast<const uint4*>(&Kp[(size_t)(col0 + r) * HD_DIM + 4 * c4]);
        Ks[r * SPAD + 4 * c4 + 0] = v.x; Ks[r * SPAD + 4 * c4 + 1] = v.y;
        Ks[r * SPAD + 4 * c4 + 2] = v.z; Ks[r * SPAD + 4 * c4 + 3] = v.w;
    }
    __syncthreads();

    float acc[2][2][4] = {};
    #pragma unroll
    for (int k = 0; k < 8; k++) {
        const int kc = k * 8 + q4;
        unsigned a[2][4], bb[2][2];
        #pragma unroll
        for (int mi = 0; mi < 2; mi++) {
            int rb = wm * 32 + mi * 16 + g;
            a[mi][0] = Qs[rb * SPAD + kc];
            a[mi][1] = Qs[(rb + 8) * SPAD + kc];
            a[mi][2] = Qs[rb * SPAD + kc + 4];
            a[mi][3] = Qs[(rb + 8) * SPAD + kc + 4];
        }
        #pragma unroll
        for (int ni = 0; ni < 2; ni++) {
            int nb = wn * 16 + ni * 8 + g;
            bb[ni][0] = Ks[nb * SPAD + kc];
            bb[ni][1] = Ks[nb * SPAD + kc + 4];
        }
        #pragma unroll
        for (int mi = 0; mi < 2; mi++)
            #pragma unroll
            for (int ni = 0; ni < 2; ni++)
                mma_tf32(acc[mi][ni], a[mi][0], a[mi][1], a[mi][2], a[mi][3],
                         bb[ni][0], bb[ni][1]);
    }

    float* Sp = g_S + (size_t)hl * TT;
    #pragma unroll
    for (int mi = 0; mi < 2; mi++) {
        #pragma unroll
        for (int ni = 0; ni < 2; ni++) {
            int r = row0 + wm * 32 + mi * 16 + g;
            int c = col0 + wn * 16 + ni * 8 + 2 * q4;
            *reinterpret_cast<float2*>(&Sp[(size_t)r * T_DIM + c]) =
                make_float2(acc[mi][ni][0], acc[mi][ni][1]);
            *reinterpret_cast<float2*>(&Sp[(size_t)(r + 8) * T_DIM + c]) =
                make_float2(acc[mi][ni][2], acc[mi][ni][3]);
        }
    }

    #pragma unroll
    for (int mi = 0; mi < 2; mi++) {
        #pragma unroll
        for (int half = 0; half < 2; half++) {
            float v0 = acc[mi][0][2 * half], v1 = acc[mi][0][2 * half + 1];
            float v2 = acc[mi][1][2 * half], v3 = acc[mi][1][2 * half + 1];
            float m = fmaxf(fmaxf(v0, v1), fmaxf(v2, v3));
            m = fmaxf(m, __shfl_xor_sync(0xffffffffu, m, 1));
            m = fmaxf(m, __shfl_xor_sync(0xffffffffu, m, 2));
            float s = __expf(v0 - m) + __expf(v1 - m) + __expf(v2 - m) + __expf(v3 - m);
            s += __shfl_xor_sync(0xffffffffu, s, 1);
            s += __shfl_xor_sync(0xffffffffu, s, 2);
            if (q4 == 0) {
                int row = wm * 32 + mi * 16 + half * 8 + g;
                sm_m[row][wn] = m;
                sm_s[row][wn] = s;
            }
        }
    }
    __syncthreads();
    if (tid < 64) {
        float m = fmaxf(fmaxf(sm_m[tid][0], sm_m[tid][1]), fmaxf(sm_m[tid][2], sm_m[tid][3]));
        float s = sm_s[tid][0] * __expf(sm_m[tid][0] - m)
                + sm_s[tid][1] * __expf(sm_m[tid][1] - m)
                + sm_s[tid][2] * __expf(sm_m[tid][2] - m)
                + sm_s[tid][3] * __expf(sm_m[tid][3] - m);
        size_t idx = ((size_t)hl * T_DIM + row0 + tid) * 32 + blockIdx.y;
        g_pm[idx] = m;
        g_ps[idx] = s;
    }
}

// =====================================================================
// Kernel 3: combine partials -> per-row max + 1/sumexp
// =====================================================================
__global__ __launch_bounds__(256) void combine_kernel()
{
    const int row = blockIdx.x * 8 + (threadIdx.x >> 5);
    const int lane = threadIdx.x & 31;
    float m = g_pm[(size_t)row * 32 + lane];
    float s = g_ps[(size_t)row * 32 + lane];
    float mm = m;
    #pragma unroll
    for (int o = 16; o > 0; o >>= 1) mm = fmaxf(mm, __shfl_xor_sync(0xffffffffu, mm, o));
    float sc = s * __expf(m - mm);
    #pragma unroll
    for (int o = 16; o > 0; o >>= 1) sc += __shfl_xor_sync(0xffffffffu, sc, o);
    if (lane == 0) { g_m[row] = mm; g_inv[row] = __frcp_rn(sc); }
}

// =====================================================================
// Kernel 4: ctx = softmax(S) @ V, split-K x4, cp.async double-buffered.
// 64-row tile, 256 thr.  P transformed (exp+cvt) once per tile in smem.
// =====================================================================
__device__ __forceinline__ void av_prefetch(const float* __restrict__ Pp,
    const float* __restrict__ Vp, int row0, int k0,
    float* Ps, float* Vs, int tid)
{
    unsigned pdst = (unsigned)__cvta_generic_to_shared(Ps);
    unsigned vdst = (unsigned)__cvta_generic_to_shared(Vs);
    #pragma unroll
    for (int i = 0; i < 2; i++) {        // P tile: 64 x 32
        int l = tid + i * 256;
        int r = l >> 3, c4 = l & 7;
        cpa16(pdst + (unsigned)(r * AV_PS + 4 * c4) * 4,
              &Pp[(size_t)(row0 + r) * T_DIM + k0 + 4 * c4]);
    }
    #pragma unroll
    for (int i = 0; i < 2; i++) {        // V tile: 32 x 64
        int l = tid + i * 256;
        int r = l >> 4, c4 = l & 15;
        cpa16(vdst + (unsigned)(r * AV_VS + 4 * c4) * 4,
              &Vp[(size_t)(k0 + r) * HD_DIM + 4 * c4]);
    }
    asm volatile("cp.async.commit_group;");
}

__global__ __launch_bounds__(256) void attnv_tf32(int b, int hg)
{
    __shared__ float Ps[2][64 * AV_PS];
    __shared__ float Vs[2][32 * AV_VS];
    __shared__ float mrow[64], irow[64];

    const int tid = threadIdx.x;
    const int lane = tid & 31, warp = tid >> 5;
    const int g = lane >> 2, q4 = lane & 3;
    const int rs = warp >> 1, nh = warp & 1;
    const int hl = blockIdx.z;
    const int ks = blockIdx.y;
    const int bh = b * H_DIM + hg * HG + hl;
    const int row0 = blockIdx.x * 64;
    const int kbase = ks * (T_DIM / KSPLIT);
    const float* Pp = g_S + (size_t)hl * TT;
    const float* Vp = g_V + (size_t)bh * T_DIM * HD_DIM;

    if (tid < 64) {
        mrow[tid] = g_m[hl * T_DIM + row0 + tid];
        irow[tid] = g_inv[hl * T_DIM + row0 + tid];
    }

    const int rb = rs * 16 + g;
    float acc[4][4] = {};

    av_prefetch(Pp, Vp, row0, kbase, Ps[0], Vs[0], tid);
    const int NC = (T_DIM / KSPLIT) / 32;          // 16
    for (int c = 0; c < NC; c++) {
        float* Pcur = Ps[c & 1];
        const unsigned* Pu = reinterpret_cast<const unsigned*>(Pcur);
        const unsigned* Vu = reinterpret_cast<const unsigned*>(Vs[c & 1]);

        asm volatile("cp.async.wait_group 0;");
        __syncthreads();

        // transform P tile in place: exp(x - m) * inv, rounded to tf32
        #pragma unroll
        for (int i = 0; i < 2; i++) {
            int l = tid + i * 256;
            int r = l >> 3, c4 = l & 7;
            float mm = mrow[r], ii = irow[r];
            float* p = &Pcur[r * AV_PS + 4 * c4];
            unsigned* pu = reinterpret_cast<unsigned*>(p);
            pu[0] = f2tf(__expf(p[0] - mm) * ii);
            pu[1] = f2tf(__expf(p[1] - mm) * ii);
            pu[2] = f2tf(__expf(p[2] - mm) * ii);
            pu[3] = f2tf(__expf(p[3] - mm) * ii);
        }
        __syncthreads();

        if (c + 1 < NC)
            av_prefetch(Pp, Vp, row0, kbase + (c + 1) * 32, Ps[(c + 1) & 1], Vs[(c + 1) & 1], tid);

        #pragma unroll
        for (int k = 0; k < 4; k++) {
            int kcc = k * 8 + q4;
            unsigned a0 = Pu[rb * AV_PS + kcc];
            unsigned a1 = Pu[(rb + 8) * AV_PS + kcc];
            unsigned a2 = Pu[rb * AV_PS + kcc + 4];
            unsigned a3 = Pu[(rb + 8) * AV_PS + kcc + 4];
            #pragma unroll
            for (int ni = 0; ni < 4; ni++) {
                int nb = nh * 32 + ni * 8 + g;
                unsigned b0 = Vu[kcc * AV_VS + nb];
                unsigned b1 = Vu[(kcc + 4) * AV_VS + nb];
                mma_tf32(acc[ni], a0, a1, a2, a3, b0, b1);
            }
        }
        __syncthreads();
    }

    float* ctx = g_ctx[ks];
    const int hglob = hg * HG + hl;
    #pragma unroll
    for (int ni = 0; ni < 4; ni++) {
        int t = row0 + rb;
        int c = hglob * HD_DIM + nh * 32 + ni * 8 + 2 * q4;
        *reinterpret_cast<float2*>(&ctx[((size_t)t * B_DIM + b) * E_DIM + c]) =
            make_float2(acc[ni][0], acc[ni][1]);
        *reinterpret_cast<float2*>(&ctx[((size_t)(t + 8) * B_DIM + b) * E_DIM + c]) =
            make_float2(acc[ni][2], acc[ni][3]);
    }
}

// =====================================================================
// Kernel 5: avg with fused exp, accumulate across head groups
// =====================================================================
__global__ __launch_bounds__(256) void avg_kernel(float* __restrict__ out_avg_b, int add)
{
    size_t idx = (size_t)blockIdx.x * blockDim.x + threadIdx.x;
    const size_t total4 = TT >> 2;
    if (idx >= total4) return;
    const int i = (int)(idx >> 9);
    const float4* base = reinterpret_cast<const float4*>(g_S) + idx;
    float4 s = make_float4(0.f, 0.f, 0.f, 0.f);
    #pragma unroll
    for (int hl = 0; hl < HG; hl++) {
        float4 v = base[(size_t)hl << 20];
        float mm = g_m[hl * T_DIM + i], ii = g_inv[hl * T_DIM + i];
        s.x += __expf(v.x - mm) * ii; s.y += __expf(v.y - mm) * ii;
        s.z += __expf(v.z - mm) * ii; s.w += __expf(v.w - mm) * ii;
    }
    s.x *= 0.125f; s.y *= 0.125f; s.z *= 0.125f; s.w *= 0.125f;
    float4* dst = reinterpret_cast<float4*>(out_avg_b) + idx;
    if (add) {
        float4 o = *dst;
        s.x += o.x; s.y += o.y; s.z += o.z; s.w += o.w;
    }
    *dst = s;
}

// =====================================================================
// Kernel 6: out projection (fp32 FFMA), ctx = sum of 4 k-slices
// =====================================================================
__global__ __launch_bounds__(256) void outproj_kernel(
    const float* __restrict__ outw, const float* __restrict__ outb,
    float* __restrict__ out)
{
    __shared__ float As[64][33];
    __shared__ float Bs[64][33];
    const int tid = threadIdx.x;
    const int tx = tid & 15, ty = tid >> 4;
    const int row0 = blockIdx.x * 64;
    const int col0 = blockIdx.y * 64;

    float acc[4][4] = {};
    for (int k0 = 0; k0 < E_DIM; k0 += 32) {
        #pragma unroll
        for (int l = tid; l < 512; l += 256) {
            int r = l >> 3, kv = l & 7;
            size_t off = (size_t)(row0 + r) * E_DIM + k0 + 4 * kv;
            float4 v0 = *reinterpret_cast<const float4*>(&g_ctx[0][off]);
            float4 v1 = *reinterpret_cast<const float4*>(&g_ctx[1][off]);
            float4 v2 = *reinterpret_cast<const float4*>(&g_ctx[2][off]);
            float4 v3 = *reinterpret_cast<const float4*>(&g_ctx[3][off]);
            As[r][4 * kv + 0] = (v0.x + v1.x) + (v2.x + v3.x);
            As[r][4 * kv + 1] = (v0.y + v1.y) + (v2.y + v3.y);
            As[r][4 * kv + 2] = (v0.z + v1.z) + (v2.z + v3.z);
            As[r][4 * kv + 3] = (v0.w + v1.w) + (v2.w + v3.w);
        }
        #pragma unroll
        for (int l = tid; l < 512; l += 256) {
            int n = l >> 3, kv = l & 7;
            float4 v = *reinterpret_cast<const float4*>(&outw[(size_t)(col0 + n) * E_DIM + k0 + 4 * kv]);
            Bs[n][4 * kv + 0] = v.x; Bs[n][4 * kv + 1] = v.y;
            Bs[n][4 * kv + 2] = v.z; Bs[n][4 * kv + 3] = v.w;
        }
        __syncthreads();
        #pragma unroll
        for (int kk = 0; kk < 32; kk++) {
            float a[4], bb[4];
            #pragma unroll
            for (int i = 0; i < 4; i++) a[i] = As[4 * ty + i][kk];
            #pragma unroll
            for (int j = 0; j < 4; j++) bb[j] = Bs[4 * tx + j][kk];
            #pragma unroll
            for (int i = 0; i < 4; i++)
                #pragma unroll
                for (int j = 0; j < 4; j++) acc[i][j] += a[i] * bb[j];
        }
        __syncthreads();
    }

    #pragma unroll
    for (int i = 0; i < 4; i++) {
        int r = row0 + 4 * ty + i;
        int n0 = col0 + 4 * tx;
        float4 v = make_float4(acc[i][0] + outb[n0 + 0], acc[i][1] + outb[n0 + 1],
                               acc[i][2] + outb[n0 + 2], acc[i][3] + outb[n0 + 3]);
        *reinterpret_cast<float4*>(&out[(size_t)r * E_DIM + n0]) = v;
    }
}

// =====================================================================
extern "C" void kernel_launch(void* const* d_in, const int* in_sizes, int n_in,
                              void* d_out, int out_size)
{
    const float* x    = (const float*)d_in[0];
    const float* W    = (const float*)d_in[1];
    const float* bias = (const float*)d_in[2];
    const float* outw = (const float*)d_in[3];
    const float* outb = (const float*)d_in[4];
    float* out = (float*)d_out;
    float* out_attn = out;
    float* out_avg  = out + (size_t)ROWS * E_DIM;

    qkv_kernel<<<dim3(ROWS / 64, (3 * E_DIM) / 64), 256>>>(x, W, bias);

    for (int b = 0; b < B_DIM; b++) {
        for (int hg = 0; hg < H_DIM / HG; hg++) {
            scores_tf32<<<dim3(T_DIM / 64, T_DIM / 64, HG), 256>>>(b, hg);
            combine_kernel<<<(HG * T_DIM) / 8, 256>>>();
            attnv_tf32<<<dim3(T_DIM / 64, KSPLIT, HG), 256>>>(b, hg);
            avg_kernel<<<(unsigned)((TT / 4 + 255) / 256), 256>>>(out_avg + (size_t)b * TT, hg);
        }
    }

    outproj_kernel<<<dim3(ROWS / 64, E_DIM / 64), 256>>>(outw, outb, out_attn);
}

// round 8
// speedup vs baseline: 1.0965x; 1.0965x over previous
#include <cuda_runtime.h>
#include <cuda_bf16.h>

// Problem constants
#define T_DIM 2048
#define B_DIM 4
#define E_DIM 512
#define H_DIM 8
#define HG 4                            // heads per group (S holds HG heads)
#define HD_DIM 64
#define BH_DIM (B_DIM * H_DIM)
#define TT ((size_t)T_DIM * T_DIM)      // 1<<22 elements
#define ROWS (T_DIM * B_DIM)            // 8192
#define SCALE 0.125f
#define SPAD 68                         // scores smem stride
#define AV_PS 36                        // attnv P smem stride (bank = 4g+q4)
#define AV_VS 72                        // attnv V smem stride (bank = 8q4+g)
#define KSPLIT 4

// ---------------- static device scratch (~186 MB) ----------------
__device__ float g_Q[(size_t)BH_DIM * T_DIM * HD_DIM];   // 16.8 MB (tf32-rounded, *SCALE)
__device__ float g_K[(size_t)BH_DIM * T_DIM * HD_DIM];   // 16.8 MB (tf32-rounded)
__device__ float g_V[(size_t)BH_DIM * T_DIM * HD_DIM];   // 16.8 MB (tf32-rounded)
__device__ float g_S[(size_t)HG * TT];                   // 67.1 MB
__device__ float g_ctx[KSPLIT][(size_t)ROWS * E_DIM];    // 67.1 MB
__device__ float g_pm[(size_t)HG * T_DIM * 32];          // 1 MB
__device__ float g_ps[(size_t)HG * T_DIM * 32];          // 1 MB
__device__ float g_m[HG * T_DIM];
__device__ float g_inv[HG * T_DIM];

// ---------------- helpers ----------------
__device__ __forceinline__ unsigned f2tf(float x) {
    unsigned u; asm("cvt.rna.tf32.f32 %0, %1;" : "=r"(u) : "f"(x)); return u;
}
__device__ __forceinline__ void mma_tf32(float* d,
    unsigned a0, unsigned a1, unsigned a2, unsigned a3,
    unsigned b0, unsigned b1)
{
    asm volatile(
        "mma.sync.aligned.m16n8k8.row.col.f32.tf32.tf32.f32 "
        "{%0,%1,%2,%3}, {%4,%5,%6,%7}, {%8,%9}, {%0,%1,%2,%3};\n"
        : "+f"(d[0]), "+f"(d[1]), "+f"(d[2]), "+f"(d[3])
        : "r"(a0), "r"(a1), "r"(a2), "r"(a3), "r"(b0), "r"(b1));
}
__device__ __forceinline__ void cpa16(unsigned dst, const float* src) {
    asm volatile("cp.async.ca.shared.global [%0], [%1], 16;" :: "r"(dst), "l"(src));
}

// =====================================================================
// Kernel 1: QKV projection (fp32 FFMA).  Outputs pre-rounded to tf32.
// =====================================================================
__global__ __launch_bounds__(256) void qkv_kernel(
    const float* __restrict__ x, const float* __restrict__ W,
    const float* __restrict__ bias)
{
    __shared__ float As[64][33];
    __shared__ float Bs[64][33];
    const int tid = threadIdx.x;
    const int tx = tid & 15, ty = tid >> 4;
    const int row0 = blockIdx.x * 64;
    const int col0 = blockIdx.y * 64;

    float acc[4][4] = {};
    for (int k0 = 0; k0 < E_DIM; k0 += 32) {
        #pragma unroll
        for (int l = tid; l < 512; l += 256) {
            int r = l >> 3, kv = l & 7;
            float4 v = *reinterpret_cast<const float4*>(&x[(size_t)(row0 + r) * E_DIM + k0 + 4 * kv]);
            As[r][4 * kv + 0] = v.x; As[r][4 * kv + 1] = v.y;
            As[r][4 * kv + 2] = v.z; As[r][4 * kv + 3] = v.w;
        }
        #pragma unroll
        for (int l = tid; l < 512; l += 256) {
            int n = l >> 3, kv = l & 7;
            float4 v = *reinterpret_cast<const float4*>(&W[(size_t)(col0 + n) * E_DIM + k0 + 4 * kv]);
            Bs[n][4 * kv + 0] = v.x; Bs[n][4 * kv + 1] = v.y;
            Bs[n][4 * kv + 2] = v.z; Bs[n][4 * kv + 3] = v.w;
        }
        __syncthreads();
        #pragma unroll
        for (int kk = 0; kk < 32; kk++) {
            float a[4], b[4];
            #pragma unroll
            for (int i = 0; i < 4; i++) a[i] = As[4 * ty + i][kk];
            #pragma unroll
            for (int j = 0; j < 4; j++) b[j] = Bs[4 * tx + j][kk];
            #pragma unroll
            for (int i = 0; i < 4; i++)
                #pragma unroll
                for (int j = 0; j < 4; j++) acc[i][j] += a[i] * b[j];
        }
        __syncthreads();
    }

    #pragma unroll
    for (int i = 0; i < 4; i++) {
        int r = row0 + 4 * ty + i;
        int t = r >> 2, b = r & 3;
        #pragma unroll
        for (int j = 0; j < 4; j++) {
            int n = col0 + 4 * tx + j;
            float val = acc[i][j] + bias[n];
            if (n < 512) {
                int h = n >> 6, d = n & 63;
                g_Q[(((size_t)(b * H_DIM + h) * T_DIM) + t) * HD_DIM + d] =
                    __uint_as_float(f2tf(val * SCALE));
            } else if (n < 1024) {
                int n2 = n - 512;
                int h = n2 >> 6, d = n2 & 63;
                g_K[(((size_t)(b * H_DIM + h) * T_DIM) + t) * HD_DIM + d] =
                    __uint_as_float(f2tf(val));
            } else {
                int n2 = n - 1024;
                int h = n2 >> 6, d = n2 & 63;
                g_V[(((size_t)(b * H_DIM + h) * T_DIM) + t) * HD_DIM + d] =
                    __uint_as_float(f2tf(val));
            }
        }
    }
}

// =====================================================================
// Kernel 2: scores (tf32 MMA, inputs pre-rounded) + fused softmax partials
// =====================================================================
__global__ __launch_bounds__(256) void scores_tf32(int b, int hg)
{
    __shared__ unsigned Qs[64 * SPAD];
    __shared__ unsigned Ks[64 * SPAD];
    __shared__ float sm_m[64][4], sm_s[64][4];
    const int tid = threadIdx.x;
    const int lane = tid & 31, warp = tid >> 5;
    const int wm = warp >> 2, wn = warp & 3;
    const int g = lane >> 2, q4 = lane & 3;
    const int hl = blockIdx.z;
    const int bh = b * H_DIM + hg * HG + hl;
    const int row0 = blockIdx.x * 64;
    const int col0 = blockIdx.y * 64;
    const unsigned* Qp = reinterpret_cast<const unsigned*>(g_Q) + (size_t)bh * T_DIM * HD_DIM;
    const unsigned* Kp = reinterpret_cast<const unsigned*>(g_K) + (size_t)bh * T_DIM * HD_DIM;

    #pragma unroll
    for (int l = tid; l < 1024; l += 256) {
        int r = l >> 4, c4 = l & 15;
        uint4 v = *reinterpret_cast<const uint4*>(&Qp[(size_t)(row0 + r) * HD_DIM + 4 * c4]);
        Qs[r * SPAD + 4 * c4 + 0] = v.x; Qs[r * SPAD + 4 * c4 + 1] = v.y;
        Qs[r * SPAD + 4 * c4 + 2] = v.z; Qs[r * SPAD + 4 * c4 + 3] = v.w;
    }
    #pragma unroll
    for (int l = tid; l < 1024; l += 256) {
        int r = l >> 4, c4 = l & 15;
        uint4 v = *reinterpret_cast<const uint4*>(&Kp[(size_t)(col0 + r) * HD_DIM + 4 * c4]);
        Ks[r * SPAD + 4 * c4 + 0] = v.x; Ks[r * SPAD + 4 * c4 + 1] = v.y;
        Ks[r * SPAD + 4 * c4 + 2] = v.z; Ks[r * SPAD + 4 * c4 + 3] = v.w;
    }
    __syncthreads();

    float acc[2][2][4] = {};
    #pragma unroll
    for (int k = 0; k < 8; k++) {
        const int kc = k * 8 + q4;
        unsigned a[2][4], bb[2][2];
        #pragma unroll
        for (int mi = 0; mi < 2; mi++) {
            int rb = wm * 32 + mi * 16 + g;
            a[mi][0] = Qs[rb * SPAD + kc];
            a[mi][1] = Qs[(rb + 8) * SPAD + kc];
            a[mi][2] = Qs[rb * SPAD + kc + 4];
            a[mi][3] = Qs[(rb + 8) * SPAD + kc + 4];
        }
        #pragma unroll
        for (int ni = 0; ni < 2; ni++) {
            int nb = wn * 16 + ni * 8 + g;
            bb[ni][0] = Ks[nb * SPAD + kc];
            bb[ni][1] = Ks[nb * SPAD + kc + 4];
        }
        #pragma unroll
        for (int mi = 0; mi < 2; mi++)
            #pragma unroll
            for (int ni = 0; ni < 2; ni++)
                mma_tf32(acc[mi][ni], a[mi][0], a[mi][1], a[mi][2], a[mi][3],
                         bb[ni][0], bb[ni][1]);
    }

    float* Sp = g_S + (size_t)hl * TT;
    #pragma unroll
    for (int mi = 0; mi < 2; mi++) {
        #pragma unroll
        for (int ni = 0; ni < 2; ni++) {
            int r = row0 + wm * 32 + mi * 16 + g;
            int c = col0 + wn * 16 + ni * 8 + 2 * q4;
            *reinterpret_cast<float2*>(&Sp[(size_t)r * T_DIM + c]) =
                make_float2(acc[mi][ni][0], acc[mi][ni][1]);
            *reinterpret_cast<float2*>(&Sp[(size_t)(r + 8) * T_DIM + c]) =
                make_float2(acc[mi][ni][2], acc[mi][ni][3]);
        }
    }

    #pragma unroll
    for (int mi = 0; mi < 2; mi++) {
        #pragma unroll
        for (int half = 0; half < 2; half++) {
            float v0 = acc[mi][0][2 * half], v1 = acc[mi][0][2 * half + 1];
            float v2 = acc[mi][1][2 * half], v3 = acc[mi][1][2 * half + 1];
            float m = fmaxf(fmaxf(v0, v1), fmaxf(v2, v3));
            m = fmaxf(m, __shfl_xor_sync(0xffffffffu, m, 1));
            m = fmaxf(m, __shfl_xor_sync(0xffffffffu, m, 2));
            float s = __expf(v0 - m) + __expf(v1 - m) + __expf(v2 - m) + __expf(v3 - m);
            s += __shfl_xor_sync(0xffffffffu, s, 1);
            s += __shfl_xor_sync(0xffffffffu, s, 2);
            if (q4 == 0) {
                int row = wm * 32 + mi * 16 + half * 8 + g;
                sm_m[row][wn] = m;
                sm_s[row][wn] = s;
            }
        }
    }
    __syncthreads();
    if (tid < 64) {
        float m = fmaxf(fmaxf(sm_m[tid][0], sm_m[tid][1]), fmaxf(sm_m[tid][2], sm_m[tid][3]));
        float s = sm_s[tid][0] * __expf(sm_m[tid][0] - m)
                + sm_s[tid][1] * __expf(sm_m[tid][1] - m)
                + sm_s[tid][2] * __expf(sm_m[tid][2] - m)
                + sm_s[tid][3] * __expf(sm_m[tid][3] - m);
        size_t idx = ((size_t)hl * T_DIM + row0 + tid) * 32 + blockIdx.y;
        g_pm[idx] = m;
        g_ps[idx] = s;
    }
}

// =====================================================================
// Kernel 3: combine partials -> per-row max + 1/sumexp
// =====================================================================
__global__ __launch_bounds__(256) void combine_kernel()
{
    const int row = blockIdx.x * 8 + (threadIdx.x >> 5);
    const int lane = threadIdx.x & 31;
    float m = g_pm[(size_t)row * 32 + lane];
    float s = g_ps[(size_t)row * 32 + lane];
    float mm = m;
    #pragma unroll
    for (int o = 16; o > 0; o >>= 1) mm = fmaxf(mm, __shfl_xor_sync(0xffffffffu, mm, o));
    float sc = s * __expf(m - mm);
    #pragma unroll
    for (int o = 16; o > 0; o >>= 1) sc += __shfl_xor_sync(0xffffffffu, sc, o);
    if (lane == 0) { g_m[row] = mm; g_inv[row] = __frcp_rn(sc); }
}

// =====================================================================
// Kernel 4: ctx = softmax(S) @ V, split-K x4, cp.async double-buffered.
// R6 pipeline (prefetch -> wait_group 1 overlap), exp fused in a-frags,
// V pre-rounded (no cvt in inner loop).  64-row tile, 256 thr.
// =====================================================================
__device__ __forceinline__ void av_prefetch(const float* __restrict__ Pp,
    const float* __restrict__ Vp, int row0, int k0,
    float* Ps, float* Vs, int tid)
{
    unsigned pdst = (unsigned)__cvta_generic_to_shared(Ps);
    unsigned vdst = (unsigned)__cvta_generic_to_shared(Vs);
    #pragma unroll
    for (int i = 0; i < 2; i++) {        // P tile: 64 x 32
        int l = tid + i * 256;
        int r = l >> 3, c4 = l & 7;
        cpa16(pdst + (unsigned)(r * AV_PS + 4 * c4) * 4,
              &Pp[(size_t)(row0 + r) * T_DIM + k0 + 4 * c4]);
    }
    #pragma unroll
    for (int i = 0; i < 2; i++) {        // V tile: 32 x 64
        int l = tid + i * 256;
        int r = l >> 4, c4 = l & 15;
        cpa16(vdst + (unsigned)(r * AV_VS + 4 * c4) * 4,
              &Vp[(size_t)(k0 + r) * HD_DIM + 4 * c4]);
    }
    asm volatile("cp.async.commit_group;");
}

__global__ __launch_bounds__(256) void attnv_tf32(int b, int hg)
{
    __shared__ float Ps[2][64 * AV_PS];
    __shared__ float Vs[2][32 * AV_VS];

    const int tid = threadIdx.x;
    const int lane = tid & 31, warp = tid >> 5;
    const int g = lane >> 2, q4 = lane & 3;
    const int rs = warp >> 1, nh = warp & 1;   // row strip (0..3), n half (0..1)
    const int hl = blockIdx.z;
    const int ks = blockIdx.y;
    const int bh = b * H_DIM + hg * HG + hl;
    const int row0 = blockIdx.x * 64;
    const int kbase = ks * (T_DIM / KSPLIT);
    const float* Pp = g_S + (size_t)hl * TT;
    const float* Vp = g_V + (size_t)bh * T_DIM * HD_DIM;

    const int rb = rs * 16 + g;
    const float m0 = g_m[hl * T_DIM + row0 + rb];
    const float i0 = g_inv[hl * T_DIM + row0 + rb];
    const float m1 = g_m[hl * T_DIM + row0 + rb + 8];
    const float i1 = g_inv[hl * T_DIM + row0 + rb + 8];

    float acc[4][4] = {};

    av_prefetch(Pp, Vp, row0, kbase, Ps[0], Vs[0], tid);
    const int NC = (T_DIM / KSPLIT) / 32;          // 16
    for (int c = 0; c < NC; c++) {
        const float* Pcur = Ps[c & 1];
        const unsigned* Vu = reinterpret_cast<const unsigned*>(Vs[c & 1]);
        if (c + 1 < NC) {
            av_prefetch(Pp, Vp, row0, kbase + (c + 1) * 32, Ps[(c + 1) & 1], Vs[(c + 1) & 1], tid);
            asm volatile("cp.async.wait_group 1;");
        } else {
            asm volatile("cp.async.wait_group 0;");
        }
        __syncthreads();

        #pragma unroll
        for (int k = 0; k < 4; k++) {
            int kcc = k * 8 + q4;
            unsigned a0 = f2tf(__expf(Pcur[rb * AV_PS + kcc] - m0) * i0);
            unsigned a1 = f2tf(__expf(Pcur[(rb + 8) * AV_PS + kcc] - m1) * i1);
            unsigned a2 = f2tf(__expf(Pcur[rb * AV_PS + kcc + 4] - m0) * i0);
            unsigned a3 = f2tf(__expf(Pcur[(rb + 8) * AV_PS + kcc + 4] - m1) * i1);
            #pragma unroll
            for (int ni = 0; ni < 4; ni++) {
                int nb = nh * 32 + ni * 8 + g;
                unsigned b0 = Vu[kcc * AV_VS + nb];
                unsigned b1 = Vu[(kcc + 4) * AV_VS + nb];
                mma_tf32(acc[ni], a0, a1, a2, a3, b0, b1);
            }
        }
        __syncthreads();
    }

    float* ctx = g_ctx[ks];
    const int hglob = hg * HG + hl;
    #pragma unroll
    for (int ni = 0; ni < 4; ni++) {
        int t = row0 + rb;
        int c = hglob * HD_DIM + nh * 32 + ni * 8 + 2 * q4;
        *reinterpret_cast<float2*>(&ctx[((size_t)t * B_DIM + b) * E_DIM + c]) =
            make_float2(acc[ni][0], acc[ni][1]);
        *reinterpret_cast<float2*>(&ctx[((size_t)(t + 8) * B_DIM + b) * E_DIM + c]) =
            make_float2(acc[ni][2], acc[ni][3]);
    }
}

// =====================================================================
// Kernel 5: avg with fused exp, accumulate across head groups
// =====================================================================
__global__ __launch_bounds__(256) void avg_kernel(float* __restrict__ out_avg_b, int add)
{
    size_t idx = (size_t)blockIdx.x * blockDim.x + threadIdx.x;
    const size_t total4 = TT >> 2;
    if (idx >= total4) return;
    const int i = (int)(idx >> 9);
    const float4* base = reinterpret_cast<const float4*>(g_S) + idx;
    float4 s = make_float4(0.f, 0.f, 0.f, 0.f);
    #pragma unroll
    for (int hl = 0; hl < HG; hl++) {
        float4 v = base[(size_t)hl << 20];
        float mm = g_m[hl * T_DIM + i], ii = g_inv[hl * T_DIM + i];
        s.x += __expf(v.x - mm) * ii; s.y += __expf(v.y - mm) * ii;
        s.z += __expf(v.z - mm) * ii; s.w += __expf(v.w - mm) * ii;
    }
    s.x *= 0.125f; s.y *= 0.125f; s.z *= 0.125f; s.w *= 0.125f;
    float4* dst = reinterpret_cast<float4*>(out_avg_b) + idx;
    if (add) {
        float4 o = *dst;
        s.x += o.x; s.y += o.y; s.z += o.z; s.w += o.w;
    }
    *dst = s;
}

// =====================================================================
// Kernel 6: out projection (fp32 FFMA), ctx = sum of 4 k-slices
// =====================================================================
__global__ __launch_bounds__(256) void outproj_kernel(
    const float* __restrict__ outw, const float* __restrict__ outb,
    float* __restrict__ out)
{
    __shared__ float As[64][33];
    __shared__ float Bs[64][33];
    const int tid = threadIdx.x;
    const int tx = tid & 15, ty = tid >> 4;
    const int row0 = blockIdx.x * 64;
    const int col0 = blockIdx.y * 64;

    float acc[4][4] = {};
    for (int k0 = 0; k0 < E_DIM; k0 += 32) {
        #pragma unroll
        for (int l = tid; l < 512; l += 256) {
            int r = l >> 3, kv = l & 7;
            size_t off = (size_t)(row0 + r) * E_DIM + k0 + 4 * kv;
            float4 v0 = *reinterpret_cast<const float4*>(&g_ctx[0][off]);
            float4 v1 = *reinterpret_cast<const float4*>(&g_ctx[1][off]);
            float4 v2 = *reinterpret_cast<const float4*>(&g_ctx[2][off]);
            float4 v3 = *reinterpret_cast<const float4*>(&g_ctx[3][off]);
            As[r][4 * kv + 0] = (v0.x + v1.x) + (v2.x + v3.x);
            As[r][4 * kv + 1] = (v0.y + v1.y) + (v2.y + v3.y);
            As[r][4 * kv + 2] = (v0.z + v1.z) + (v2.z + v3.z);
            As[r][4 * kv + 3] = (v0.w + v1.w) + (v2.w + v3.w);
        }
        #pragma unroll
        for (int l = tid; l < 512; l += 256) {
            int n = l >> 3, kv = l & 7;
            float4 v = *reinterpret_cast<const float4*>(&outw[(size_t)(col0 + n) * E_DIM + k0 + 4 * kv]);
            Bs[n][4 * kv + 0] = v.x; Bs[n][4 * kv + 1] = v.y;
            Bs[n][4 * kv + 2] = v.z; Bs[n][4 * kv + 3] = v.w;
        }
        __syncthreads();
        #pragma unroll
        for (int kk = 0; kk < 32; kk++) {
            float a[4], bb[4];
            #pragma unroll
            for (int i = 0; i < 4; i++) a[i] = As[4 * ty + i][kk];
            #pragma unroll
            for (int j = 0; j < 4; j++) bb[j] = Bs[4 * tx + j][kk];
            #pragma unroll
            for (int i = 0; i < 4; i++)
                #pragma unroll
                for (int j = 0; j < 4; j++) acc[i][j] += a[i] * bb[j];
        }
        __syncthreads();
    }

    #pragma unroll
    for (int i = 0; i < 4; i++) {
        int r = row0 + 4 * ty + i;
        int n0 = col0 + 4 * tx;
        float4 v = make_float4(acc[i][0] + outb[n0 + 0], acc[i][1] + outb[n0 + 1],
                               acc[i][2] + outb[n0 + 2], acc[i][3] + outb[n0 + 3]);
        *reinterpret_cast<float4*>(&out[(size_t)r * E_DIM + n0]) = v;
    }
}

// =====================================================================
extern "C" void kernel_launch(void* const* d_in, const int* in_sizes, int n_in,
                              void* d_out, int out_size)
{
    const float* x    = (const float*)d_in[0];
    const float* W    = (const float*)d_in[1];
    const float* bias = (const float*)d_in[2];
    const float* outw = (const float*)d_in[3];
    const float* outb = (const float*)d_in[4];
    float* out = (float*)d_out;
    float* out_attn = out;
    float* out_avg  = out + (size_t)ROWS * E_DIM;

    qkv_kernel<<<dim3(ROWS / 64, (3 * E_DIM) / 64), 256>>>(x, W, bias);

    for (int b = 0; b < B_DIM; b++) {
        for (int hg = 0; hg < H_DIM / HG; hg++) {
            scores_tf32<<<dim3(T_DIM / 64, T_DIM / 64, HG), 256>>>(b, hg);
            combine_kernel<<<(HG * T_DIM) / 8, 256>>>();
            attnv_tf32<<<dim3(T_DIM / 64, KSPLIT, HG), 256>>>(b, hg);
            avg_kernel<<<(unsigned)((TT / 4 + 255) / 256), 256>>>(out_avg + (size_t)b * TT, hg);
        }
    }

    outproj_kernel<<<dim3(ROWS / 64, E_DIM / 64), 256>>>(outw, outb, out_attn);
}

// round 9
// speedup vs baseline: 1.1308x; 1.0313x over previous
#include <cuda_runtime.h>
#include <cuda_bf16.h>

// Problem constants
#define T_DIM 2048
#define B_DIM 4
#define E_DIM 512
#define H_DIM 8
#define HG 4                            // heads per group (S holds HG heads)
#define HD_DIM 64
#define BH_DIM (B_DIM * H_DIM)
#define TT ((size_t)T_DIM * T_DIM)      // 1<<22 elements
#define ROWS (T_DIM * B_DIM)            // 8192
#define SCALE 0.125f
#define SPAD 68                         // scores smem stride
#define AV_PS 36                        // attnv P smem stride (bank = 4g+q4)
#define AV_VS 72                        // attnv V smem stride (bank = 8q4+g)
#define KSPLIT 4

// ---------------- static device scratch (~185 MB) ----------------
// g_S now holds E = tf32-rounded exp(score) (max-free softmax numerator).
__device__ float g_Q[(size_t)BH_DIM * T_DIM * HD_DIM];   // 16.8 MB (tf32-rounded, *SCALE)
__device__ float g_K[(size_t)BH_DIM * T_DIM * HD_DIM];   // 16.8 MB (tf32-rounded)
__device__ float g_V[(size_t)BH_DIM * T_DIM * HD_DIM];   // 16.8 MB (tf32-rounded)
__device__ float g_S[(size_t)HG * TT];                   // 67.1 MB
__device__ float g_ctx[KSPLIT][(size_t)ROWS * E_DIM];    // 67.1 MB
__device__ float g_ps[(size_t)HG * T_DIM * 32];          // 1 MB row-sum partials
__device__ float g_inv[HG * T_DIM];                      // per-row 1/sum

// ---------------- helpers ----------------
__device__ __forceinline__ unsigned f2tf(float x) {
    unsigned u; asm("cvt.rna.tf32.f32 %0, %1;" : "=r"(u) : "f"(x)); return u;
}
__device__ __forceinline__ void mma_tf32(float* d,
    unsigned a0, unsigned a1, unsigned a2, unsigned a3,
    unsigned b0, unsigned b1)
{
    asm volatile(
        "mma.sync.aligned.m16n8k8.row.col.f32.tf32.tf32.f32 "
        "{%0,%1,%2,%3}, {%4,%5,%6,%7}, {%8,%9}, {%0,%1,%2,%3};\n"
        : "+f"(d[0]), "+f"(d[1]), "+f"(d[2]), "+f"(d[3])
        : "r"(a0), "r"(a1), "r"(a2), "r"(a3), "r"(b0), "r"(b1));
}
__device__ __forceinline__ void cpa16(unsigned dst, const float* src) {
    asm volatile("cp.async.ca.shared.global [%0], [%1], 16;" :: "r"(dst), "l"(src));
}

// =====================================================================
// Kernel 1: QKV projection (fp32 FFMA).  Outputs pre-rounded to tf32.
// =====================================================================
__global__ __launch_bounds__(256) void qkv_kernel(
    const float* __restrict__ x, const float* __restrict__ W,
    const float* __restrict__ bias)
{
    __shared__ float As[64][33];
    __shared__ float Bs[64][33];
    const int tid = threadIdx.x;
    const int tx = tid & 15, ty = tid >> 4;
    const int row0 = blockIdx.x * 64;
    const int col0 = blockIdx.y * 64;

    float acc[4][4] = {};
    for (int k0 = 0; k0 < E_DIM; k0 += 32) {
        #pragma unroll
        for (int l = tid; l < 512; l += 256) {
            int r = l >> 3, kv = l & 7;
            float4 v = *reinterpret_cast<const float4*>(&x[(size_t)(row0 + r) * E_DIM + k0 + 4 * kv]);
            As[r][4 * kv + 0] = v.x; As[r][4 * kv + 1] = v.y;
            As[r][4 * kv + 2] = v.z; As[r][4 * kv + 3] = v.w;
        }
        #pragma unroll
        for (int l = tid; l < 512; l += 256) {
            int n = l >> 3, kv = l & 7;
            float4 v = *reinterpret_cast<const float4*>(&W[(size_t)(col0 + n) * E_DIM + k0 + 4 * kv]);
            Bs[n][4 * kv + 0] = v.x; Bs[n][4 * kv + 1] = v.y;
            Bs[n][4 * kv + 2] = v.z; Bs[n][4 * kv + 3] = v.w;
        }
        __syncthreads();
        #pragma unroll
        for (int kk = 0; kk < 32; kk++) {
            float a[4], b[4];
            #pragma unroll
            for (int i = 0; i < 4; i++) a[i] = As[4 * ty + i][kk];
            #pragma unroll
            for (int j = 0; j < 4; j++) b[j] = Bs[4 * tx + j][kk];
            #pragma unroll
            for (int i = 0; i < 4; i++)
                #pragma unroll
                for (int j = 0; j < 4; j++) acc[i][j] += a[i] * b[j];
        }
        __syncthreads();
    }

    #pragma unroll
    for (int i = 0; i < 4; i++) {
        int r = row0 + 4 * ty + i;
        int t = r >> 2, b = r & 3;
        #pragma unroll
        for (int j = 0; j < 4; j++) {
            int n = col0 + 4 * tx + j;
            float val = acc[i][j] + bias[n];
            if (n < 512) {
                int h = n >> 6, d = n & 63;
                g_Q[(((size_t)(b * H_DIM + h) * T_DIM) + t) * HD_DIM + d] =
                    __uint_as_float(f2tf(val * SCALE));
            } else if (n < 1024) {
                int n2 = n - 512;
                int h = n2 >> 6, d = n2 & 63;
                g_K[(((size_t)(b * H_DIM + h) * T_DIM) + t) * HD_DIM + d] =
                    __uint_as_float(f2tf(val));
            } else {
                int n2 = n - 1024;
                int h = n2 >> 6, d = n2 & 63;
                g_V[(((size_t)(b * H_DIM + h) * T_DIM) + t) * HD_DIM + d] =
                    __uint_as_float(f2tf(val));
            }
        }
    }
}

// =====================================================================
// Kernel 2: scores (tf32 MMA) -> E = tf32(exp(s)) + fused row-sum partials
// =====================================================================
__global__ __launch_bounds__(256) void scores_tf32(int b, int hg)
{
    __shared__ unsigned Qs[64 * SPAD];
    __shared__ unsigned Ks[64 * SPAD];
    __shared__ float sm_s[64][4];
    const int tid = threadIdx.x;
    const int lane = tid & 31, warp = tid >> 5;
    const int wm = warp >> 2, wn = warp & 3;
    const int g = lane >> 2, q4 = lane & 3;
    const int hl = blockIdx.z;
    const int bh = b * H_DIM + hg * HG + hl;
    const int row0 = blockIdx.x * 64;
    const int col0 = blockIdx.y * 64;
    const unsigned* Qp = reinterpret_cast<const unsigned*>(g_Q) + (size_t)bh * T_DIM * HD_DIM;
    const unsigned* Kp = reinterpret_cast<const unsigned*>(g_K) + (size_t)bh * T_DIM * HD_DIM;

    #pragma unroll
    for (int l = tid; l < 1024; l += 256) {
        int r = l >> 4, c4 = l & 15;
        uint4 v = *reinterpret_cast<const uint4*>(&Qp[(size_t)(row0 + r) * HD_DIM + 4 * c4]);
        Qs[r * SPAD + 4 * c4 + 0] = v.x; Qs[r * SPAD + 4 * c4 + 1] = v.y;
        Qs[r * SPAD + 4 * c4 + 2] = v.z; Qs[r * SPAD + 4 * c4 + 3] = v.w;
    }
    #pragma unroll
    for (int l = tid; l < 1024; l += 256) {
        int r = l >> 4, c4 = l & 15;
        uint4 v = *reinterpret_cast<const uint4*>(&Kp[(size_t)(col0 + r) * HD_DIM + 4 * c4]);
        Ks[r * SPAD + 4 * c4 + 0] = v.x; Ks[r * SPAD + 4 * c4 + 1] = v.y;
        Ks[r * SPAD + 4 * c4 + 2] = v.z; Ks[r * SPAD + 4 * c4 + 3] = v.w;
    }
    __syncthreads();

    float acc[2][2][4] = {};
    #pragma unroll
    for (int k = 0; k < 8; k++) {
        const int kc = k * 8 + q4;
        unsigned a[2][4], bb[2][2];
        #pragma unroll
        for (int mi = 0; mi < 2; mi++) {
            int rb = wm * 32 + mi * 16 + g;
            a[mi][0] = Qs[rb * SPAD + kc];
            a[mi][1] = Qs[(rb + 8) * SPAD + kc];
            a[mi][2] = Qs[rb * SPAD + kc + 4];
            a[mi][3] = Qs[(rb + 8) * SPAD + kc + 4];
        }
        #pragma unroll
        for (int ni = 0; ni < 2; ni++) {
            int nb = wn * 16 + ni * 8 + g;
            bb[ni][0] = Ks[nb * SPAD + kc];
            bb[ni][1] = Ks[nb * SPAD + kc + 4];
        }
        #pragma unroll
        for (int mi = 0; mi < 2; mi++)
            #pragma unroll
            for (int ni = 0; ni < 2; ni++)
                mma_tf32(acc[mi][ni], a[mi][0], a[mi][1], a[mi][2], a[mi][3],
                         bb[ni][0], bb[ni][1]);
    }

    // E = tf32(exp(s)); store + row-sum partials of the rounded values
    float ev[2][2][4];
    #pragma unroll
    for (int mi = 0; mi < 2; mi++)
        #pragma unroll
        for (int ni = 0; ni < 2; ni++)
            #pragma unroll
            for (int j = 0; j < 4; j++)
                ev[mi][ni][j] = __uint_as_float(f2tf(__expf(acc[mi][ni][j])));

    float* Sp = g_S + (size_t)hl * TT;
    #pragma unroll
    for (int mi = 0; mi < 2; mi++) {
        #pragma unroll
        for (int ni = 0; ni < 2; ni++) {
            int r = row0 + wm * 32 + mi * 16 + g;
            int c = col0 + wn * 16 + ni * 8 + 2 * q4;
            *reinterpret_cast<float2*>(&Sp[(size_t)r * T_DIM + c]) =
                make_float2(ev[mi][ni][0], ev[mi][ni][1]);
            *reinterpret_cast<float2*>(&Sp[(size_t)(r + 8) * T_DIM + c]) =
                make_float2(ev[mi][ni][2], ev[mi][ni][3]);
        }
    }

    #pragma unroll
    for (int mi = 0; mi < 2; mi++) {
        #pragma unroll
        for (int half = 0; half < 2; half++) {
            float s = (ev[mi][0][2 * half] + ev[mi][0][2 * half + 1])
                    + (ev[mi][1][2 * half] + ev[mi][1][2 * half + 1]);
            s += __shfl_xor_sync(0xffffffffu, s, 1);
            s += __shfl_xor_sync(0xffffffffu, s, 2);
            if (q4 == 0)
                sm_s[wm * 32 + mi * 16 + half * 8 + g][wn] = s;
        }
    }
    __syncthreads();
    if (tid < 64) {
        float s = (sm_s[tid][0] + sm_s[tid][1]) + (sm_s[tid][2] + sm_s[tid][3]);
        g_ps[((size_t)hl * T_DIM + row0 + tid) * 32 + blockIdx.y] = s;
    }
}

// =====================================================================
// Kernel 3: combine partials -> per-row 1/sum
// =====================================================================
__global__ __launch_bounds__(256) void combine_kernel()
{
    const int row = blockIdx.x * 8 + (threadIdx.x >> 5);
    const int lane = threadIdx.x & 31;
    float s = g_ps[(size_t)row * 32 + lane];
    #pragma unroll
    for (int o = 16; o > 0; o >>= 1) s += __shfl_xor_sync(0xffffffffu, s, o);
    if (lane == 0) g_inv[row] = __frcp_rn(s);
}

// =====================================================================
// Kernel 4: ctx = (E @ V) * inv, split-K x4, cp.async double-buffered.
// Inner loop is pure LDS + MMA (E pre-exponentiated & tf32-rounded).
// =====================================================================
__device__ __forceinline__ void av_prefetch(const float* __restrict__ Pp,
    const float* __restrict__ Vp, int row0, int k0,
    float* Ps, float* Vs, int tid)
{
    unsigned pdst = (unsigned)__cvta_generic_to_shared(Ps);
    unsigned vdst = (unsigned)__cvta_generic_to_shared(Vs);
    #pragma unroll
    for (int i = 0; i < 2; i++) {        // E tile: 64 x 32
        int l = tid + i * 256;
        int r = l >> 3, c4 = l & 7;
        cpa16(pdst + (unsigned)(r * AV_PS + 4 * c4) * 4,
              &Pp[(size_t)(row0 + r) * T_DIM + k0 + 4 * c4]);
    }
    #pragma unroll
    for (int i = 0; i < 2; i++) {        // V tile: 32 x 64
        int l = tid + i * 256;
        int r = l >> 4, c4 = l & 15;
        cpa16(vdst + (unsigned)(r * AV_VS + 4 * c4) * 4,
              &Vp[(size_t)(k0 + r) * HD_DIM + 4 * c4]);
    }
    asm volatile("cp.async.commit_group;");
}

__global__ __launch_bounds__(256) void attnv_tf32(int b, int hg)
{
    __shared__ float Ps[2][64 * AV_PS];
    __shared__ float Vs[2][32 * AV_VS];

    const int tid = threadIdx.x;
    const int lane = tid & 31, warp = tid >> 5;
    const int g = lane >> 2, q4 = lane & 3;
    const int rs = warp >> 1, nh = warp & 1;   // row strip (0..3), n half (0..1)
    const int hl = blockIdx.z;
    const int ks = blockIdx.y;
    const int bh = b * H_DIM + hg * HG + hl;
    const int row0 = blockIdx.x * 64;
    const int kbase = ks * (T_DIM / KSPLIT);
    const float* Pp = g_S + (size_t)hl * TT;
    const float* Vp = g_V + (size_t)bh * T_DIM * HD_DIM;

    const int rb = rs * 16 + g;
    float acc[4][4] = {};

    av_prefetch(Pp, Vp, row0, kbase, Ps[0], Vs[0], tid);
    const int NC = (T_DIM / KSPLIT) / 32;          // 16
    for (int c = 0; c < NC; c++) {
        const unsigned* Pu = reinterpret_cast<const unsigned*>(Ps[c & 1]);
        const unsigned* Vu = reinterpret_cast<const unsigned*>(Vs[c & 1]);
        if (c + 1 < NC) {
            av_prefetch(Pp, Vp, row0, kbase + (c + 1) * 32, Ps[(c + 1) & 1], Vs[(c + 1) & 1], tid);
            asm volatile("cp.async.wait_group 1;");
        } else {
            asm volatile("cp.async.wait_group 0;");
        }
        __syncthreads();

        #pragma unroll
        for (int k = 0; k < 4; k++) {
            int kcc = k * 8 + q4;
            unsigned a0 = Pu[rb * AV_PS + kcc];
            unsigned a1 = Pu[(rb + 8) * AV_PS + kcc];
            unsigned a2 = Pu[rb * AV_PS + kcc + 4];
            unsigned a3 = Pu[(rb + 8) * AV_PS + kcc + 4];
            #pragma unroll
            for (int ni = 0; ni < 4; ni++) {
                int nb = nh * 32 + ni * 8 + g;
                unsigned b0 = Vu[kcc * AV_VS + nb];
                unsigned b1 = Vu[(kcc + 4) * AV_VS + nb];
                mma_tf32(acc[ni], a0, a1, a2, a3, b0, b1);
            }
        }
        __syncthreads();
    }

    // normalize: rows rb (acc[ni][0..1]) and rb+8 (acc[ni][2..3])
    const float i0 = g_inv[hl * T_DIM + row0 + rb];
    const float i1 = g_inv[hl * T_DIM + row0 + rb + 8];

    float* ctx = g_ctx[ks];
    const int hglob = hg * HG + hl;
    #pragma unroll
    for (int ni = 0; ni < 4; ni++) {
        int t = row0 + rb;
        int c = hglob * HD_DIM + nh * 32 + ni * 8 + 2 * q4;
        *reinterpret_cast<float2*>(&ctx[((size_t)t * B_DIM + b) * E_DIM + c]) =
            make_float2(acc[ni][0] * i0, acc[ni][1] * i0);
        *reinterpret_cast<float2*>(&ctx[((size_t)(t + 8) * B_DIM + b) * E_DIM + c]) =
            make_float2(acc[ni][2] * i1, acc[ni][3] * i1);
    }
}

// =====================================================================
// Kernel 5: avg = (1/8) sum_h E[h] * inv[h], accumulate across groups
// =====================================================================
__global__ __launch_bounds__(256) void avg_kernel(float* __restrict__ out_avg_b, int add)
{
    size_t idx = (size_t)blockIdx.x * blockDim.x + threadIdx.x;
    const size_t total4 = TT >> 2;
    if (idx >= total4) return;
    const int i = (int)(idx >> 9);
    const float4* base = reinterpret_cast<const float4*>(g_S) + idx;
    float4 s = make_float4(0.f, 0.f, 0.f, 0.f);
    #pragma unroll
    for (int hl = 0; hl < HG; hl++) {
        float4 v = base[(size_t)hl << 20];
        float ii = g_inv[hl * T_DIM + i];
        s.x += v.x * ii; s.y += v.y * ii;
        s.z += v.z * ii; s.w += v.w * ii;
    }
    s.x *= 0.125f; s.y *= 0.125f; s.z *= 0.125f; s.w *= 0.125f;
    float4* dst = reinterpret_cast<float4*>(out_avg_b) + idx;
    if (add) {
        float4 o = *dst;
        s.x += o.x; s.y += o.y; s.z += o.z; s.w += o.w;
    }
    *dst = s;
}

// =====================================================================
// Kernel 6: out projection (fp32 FFMA), ctx = sum of 4 k-slices
// =====================================================================
__global__ __launch_bounds__(256) void outproj_kernel(
    const float* __restrict__ outw, const float* __restrict__ outb,
    float* __restrict__ out)
{
    __shared__ float As[64][33];
    __shared__ float Bs[64][33];
    const int tid = threadIdx.x;
    const int tx = tid & 15, ty = tid >> 4;
    const int row0 = blockIdx.x * 64;
    const int col0 = blockIdx.y * 64;

    float acc[4][4] = {};
    for (int k0 = 0; k0 < E_DIM; k0 += 32) {
        #pragma unroll
        for (int l = tid; l < 512; l += 256) {
            int r = l >> 3, kv = l & 7;
            size_t off = (size_t)(row0 + r) * E_DIM + k0 + 4 * kv;
            float4 v0 = *reinterpret_cast<const float4*>(&g_ctx[0][off]);
            float4 v1 = *reinterpret_cast<const float4*>(&g_ctx[1][off]);
            float4 v2 = *reinterpret_cast<const float4*>(&g_ctx[2][off]);
            float4 v3 = *reinterpret_cast<const float4*>(&g_ctx[3][off]);
            As[r][4 * kv + 0] = (v0.x + v1.x) + (v2.x + v3.x);
            As[r][4 * kv + 1] = (v0.y + v1.y) + (v2.y + v3.y);
            As[r][4 * kv + 2] = (v0.z + v1.z) + (v2.z + v3.z);
            As[r][4 * kv + 3] = (v0.w + v1.w) + (v2.w + v3.w);
        }
        #pragma unroll
        for (int l = tid; l < 512; l += 256) {
            int n = l >> 3, kv = l & 7;
            float4 v = *reinterpret_cast<const float4*>(&outw[(size_t)(col0 + n) * E_DIM + k0 + 4 * kv]);
            Bs[n][4 * kv + 0] = v.x; Bs[n][4 * kv + 1] = v.y;
            Bs[n][4 * kv + 2] = v.z; Bs[n][4 * kv + 3] = v.w;
        }
        __syncthreads();
        #pragma unroll
        for (int kk = 0; kk < 32; kk++) {
            float a[4], bb[4];
            #pragma unroll
            for (int i = 0; i < 4; i++) a[i] = As[4 * ty + i][kk];
            #pragma unroll
            for (int j = 0; j < 4; j++) bb[j] = Bs[4 * tx + j][kk];
            #pragma unroll
            for (int i = 0; i < 4; i++)
                #pragma unroll
                for (int j = 0; j < 4; j++) acc[i][j] += a[i] * bb[j];
        }
        __syncthreads();
    }

    #pragma unroll
    for (int i = 0; i < 4; i++) {
        int r = row0 + 4 * ty + i;
        int n0 = col0 + 4 * tx;
        float4 v = make_float4(acc[i][0] + outb[n0 + 0], acc[i][1] + outb[n0 + 1],
                               acc[i][2] + outb[n0 + 2], acc[i][3] + outb[n0 + 3]);
        *reinterpret_cast<float4*>(&out[(size_t)r * E_DIM + n0]) = v;
    }
}

// =====================================================================
extern "C" void kernel_launch(void* const* d_in, const int* in_sizes, int n_in,
                              void* d_out, int out_size)
{
    const float* x    = (const float*)d_in[0];
    const float* W    = (const float*)d_in[1];
    const float* bias = (const float*)d_in[2];
    const float* outw = (const float*)d_in[3];
    const float* outb = (const float*)d_in[4];
    float* out = (float*)d_out;
    float* out_attn = out;
    float* out_avg  = out + (size_t)ROWS * E_DIM;

    qkv_kernel<<<dim3(ROWS / 64, (3 * E_DIM) / 64), 256>>>(x, W, bias);

    for (int b = 0; b < B_DIM; b++) {
        for (int hg = 0; hg < H_DIM / HG; hg++) {
            scores_tf32<<<dim3(T_DIM / 64, T_DIM / 64, HG), 256>>>(b, hg);
            combine_kernel<<<(HG * T_DIM) / 8, 256>>>();
            attnv_tf32<<<dim3(T_DIM / 64, KSPLIT, HG), 256>>>(b, hg);
            avg_kernel<<<(unsigned)((TT / 4 + 255) / 256), 256>>>(out_avg + (size_t)b * TT, hg);
        }
    }

    outproj_kernel<<<dim3(ROWS / 64, E_DIM / 64), 256>>>(outw, outb, out_attn);
}